// round 15
// baseline (speedup 1.0000x reference)
#include <cuda_runtime.h>
#include <cstdint>

namespace {

constexpr int IMG_H  = 512;
constexpr int IMG_W  = 512;
constexpr int NPLANE = 48;            // 16 * 3
constexpr int TILE_W = 256;           // thread t owns cols t and t+128
constexpr int TILE_H = 64;
constexpr int THREADS = 128;
constexpr int HALO = 5;
constexpr int IN_ROWS = TILE_H + 2 * HALO;          // 74 input rows needed
constexpr int NGROUPS = (IN_ROWS + 10) / 11;        // 7 groups of <=11 staged rows
constexpr int NPAIR = TILE_W / 2 + 2 * HALO;        // 138 interleaved pairs per row
constexpr int GRID_X = IMG_W / TILE_W;              // 2
constexpr int GRID_Y = IMG_H / TILE_H;              // 8
constexpr int NBLOCKS = GRID_X * GRID_Y * NPLANE;   // 768
constexpr float C1v = 0.01f * 0.01f;
constexpr float C2v = 0.03f * 0.03f;
constexpr double NPIX = 12582912.0;                 // 16*3*512*512

__device__ constexpr float GW[11] = {
    0.0010283784f, 0.0075987582f, 0.0360008038f, 0.1093606949f, 0.2130055428f,
    0.2660117149f, 0.2130055428f, 0.1093606949f, 0.0360008038f, 0.0075987582f,
    0.0010283784f};

} // namespace

// ---- packed f32x2 helpers (SASS FFMA2 / FMUL2 / FADD2 — PTX-only forms) ----
typedef unsigned long long u64;
#define FMA2(d, a, b, c) \
    asm("fma.rn.f32x2 %0, %1, %2, %3;" : "=l"(d) : "l"(a), "l"(b), "l"(c))
#define MUL2(d, a, b) \
    asm("mul.rn.f32x2 %0, %1, %2;" : "=l"(d) : "l"(a), "l"(b))
#define ADD2(d, a, b) \
    asm("add.rn.f32x2 %0, %1, %2;" : "=l"(d) : "l"(a), "l"(b))
#define PACK2(d, lo, hi) \
    asm("mov.b64 %0, {%1, %2};" : "=l"(d) : "r"(__float_as_uint(lo)), "r"(__float_as_uint(hi)))
#define UNPACK2(lo, hi, d) \
    do { unsigned _ulo, _uhi; \
         asm("mov.b64 {%0, %1}, %2;" : "=r"(_ulo), "=r"(_uhi) : "l"(d)); \
         lo = __uint_as_float(_ulo); hi = __uint_as_float(_uhi); } while (0)

// ---- cp.async (LDGSTS) helpers: 4B copy with zero-fill when src_size==0 ----
#define CP4(dst_u32, src_ptr, sz) \
    asm volatile("cp.async.ca.shared.global [%0], [%1], 4, %2;" \
                 :: "r"(dst_u32), "l"(src_ptr), "r"(sz))
#define CP_COMMIT() asm volatile("cp.async.commit_group;")
#define CP_WAIT1()  asm volatile("cp.async.wait_group 1;")
#define CP_WAIT0()  asm volatile("cp.async.wait_group 0;")

__device__ float g_partials[NBLOCKS * 2];
__device__ unsigned int g_count = 0;

__global__ __launch_bounds__(THREADS, 4)
void ssim_main(const float* __restrict__ img1, const float* __restrict__ img2,
               float* __restrict__ out) {
    // Double-buffered interleaved pair layout (R10-proven):
    // sbuf[buf][arr][j][i] = pack(v[row, c0+i-5], v[row, c0+i+123]).
    __shared__ u64 sbuf[2][2][11][NPAIR];     // 48,576 B
    __shared__ float sred[8];
    __shared__ bool s_last;

    const int tid = threadIdx.x;
    const int c0 = blockIdx.x * TILE_W;
    const int r0 = blockIdx.y * TILE_H;
    const float* p1 = img1 + (size_t)blockIdx.z * (IMG_H * IMG_W);
    const float* p2 = img2 + (size_t)blockIdx.z * (IMG_H * IMG_W);
    const bool left_blk = (blockIdx.x == 0);
    const bool rows_interior = (r0 >= HALO) && (r0 + TILE_H + HALO <= IMG_H);

    unsigned smem_base;
    asm("{ .reg .u64 t; cvta.to.shared.u64 t, %1; cvt.u32.u64 %0, t; }"
        : "=r"(smem_base) : "l"(&sbuf[0][0][0][0]));

    // Stage group g into buffer b via cp.async. No integer division: j-outer
    // loop, two strided column elements per thread (138 = 128 + 10). Edge
    // predicates are uniform-cheap: only the left image edge zero-fills A in
    // phase 1 (tid<5), only the right image edge zero-fills B in phase 2
    // (tid>=5). Correctness validated in R12.
    auto stage = [&](int g, int b) {
        const int rows_g = (g == NGROUPS - 1) ? (IN_ROWS - g * 11) : 11;
        const int rbase = r0 - HALO + g * 11;
        for (int j = 0; j < rows_g; ++j) {
            const int gr = rbase + j;
            const bool rin = rows_interior || ((unsigned)gr < (unsigned)IMG_H);
            const float* r1 = p1 + (rin ? gr : 0) * IMG_W;
            const float* r2 = p2 + (rin ? gr : 0) * IMG_W;
            const unsigned dx = smem_base +
                (unsigned)((((b * 2 + 0) * 11 + j) * NPAIR) * 8);
            const unsigned dy = smem_base +
                (unsigned)((((b * 2 + 1) * 11 + j) * NPAIR) * 8);
            {   // element i = tid: A oob only at left image edge
                const unsigned szA = (rin && !(left_blk && tid < HALO)) ? 4u : 0u;
                const unsigned szB = rin ? 4u : 0u;
                const int oA = szA ? (c0 + tid - HALO) : 0;
                const int oB = szB ? (c0 + tid - HALO + 128) : 0;
                CP4(dx + tid * 8u,      r1 + oA, szA);
                CP4(dx + tid * 8u + 4u, r1 + oB, szB);
                CP4(dy + tid * 8u,      r2 + oA, szA);
                CP4(dy + tid * 8u + 4u, r2 + oB, szB);
            }
            if (tid < NPAIR - THREADS) {   // element i = tid+128
                const int i = tid + THREADS;
                const unsigned szA = rin ? 4u : 0u;
                const unsigned szB = (rin && !(!left_blk && tid >= HALO)) ? 4u : 0u;
                const int oA = szA ? (c0 + i - HALO) : 0;
                const int oB = szB ? (c0 + i - HALO + 128) : 0;
                CP4(dx + i * 8u,      r1 + oA, szA);
                CP4(dx + i * 8u + 4u, r1 + oB, szB);
                CP4(dy + i * 8u,      r2 + oA, szA);
                CP4(dy + i * 8u + 4u, r2 + oB, szB);
            }
        }
        CP_COMMIT();
    };

    // 6 unique packed Gaussian weights (symmetric window).
    u64 wp[6];
#pragma unroll
    for (int k = 0; k < 6; ++k) PACK2(wp[k], GW[k], GW[k]);
    u64 NEG1p, C1p, C2p, TWOp;
    PACK2(NEG1p, -1.f, -1.f);
    PACK2(C1p, C1v, C1v);
    PACK2(C2p, C2v, C2v);
    PACK2(TWOp, 2.f, 2.f);

    // Vertical ring accumulators (packed), slot = output_row % 11.
    u64 a1p[11], a2p[11], assp[11], axyp[11];
#pragma unroll
    for (int i = 0; i < 11; ++i) {
        a1p[i] = 0ull; a2p[i] = 0ull; assp[i] = 0ull; axyp[i] = 0ull;
    }

    float ssim_sum = 0.f;
    u64 l1p = 0ull;   // packed |x-y| accumulator

    stage(0, 0);

    for (int t = 0; t < NGROUPS; ++t) {
        const int buf = t & 1;
        if (t + 1 < NGROUPS) {
            stage(t + 1, buf ^ 1);   // overlap next group's loads with compute
            CP_WAIT1();              // group t's data landed
        } else {
            CP_WAIT0();
        }
        __syncthreads();             // all threads' group-t cp.asyncs complete

#pragma unroll
        for (int j = 0; j < 11; ++j) {
            const int ir = t * 11 + j;   // staged input row index
            if (ir >= IN_ROWS) break;

            // Horizontal 11-tap conv of x, y, x^2+y^2, x*y — every tap is one
            // aligned LDS.64 that IS the packed operand.
            u64 hx, hy, hss, hxy;
            u64 l1x, l1y;
#pragma unroll
            for (int k = 0; k < 11; ++k) {
                const u64 xp = sbuf[buf][0][j][tid + k];
                const u64 yp = sbuf[buf][1][j][tid + k];
                if (k == HALO) { l1x = xp; l1y = yp; }
                u64 ssq, pxy, txx;
                MUL2(txx, xp, xp);
                FMA2(ssq, yp, yp, txx);      // x^2 + y^2
                MUL2(pxy, xp, yp);
                const u64 w = wp[k < 6 ? k : 10 - k];
                if (k == 0) {
                    MUL2(hx, w, xp);  MUL2(hy, w, yp);
                    MUL2(hss, w, ssq); MUL2(hxy, w, pxy);
                } else {
                    FMA2(hx,  w, xp,  hx);
                    FMA2(hy,  w, yp,  hy);
                    FMA2(hss, w, ssq, hss);
                    FMA2(hxy, w, pxy, hxy);
                }
            }

            // L1 term: once per pixel (both lanes at once).
            if (ir >= HALO && ir < TILE_H + HALO) {
                u64 d;
                FMA2(d, l1y, NEG1p, l1x);                  // x - y
                d &= 0x7FFFFFFF7FFFFFFFull;                // |.| per lane
                ADD2(l1p, l1p, d);
            }

            // Vertical ring accumulation (packed). slot = (ir - dy) % 11, static.
#pragma unroll
            for (int dy = 0; dy < 11; ++dy) {
                const int s = (j - dy + 11) % 11;
                const u64 w = wp[dy < 6 ? dy : 10 - dy];
                if (dy == 0) {   // first touch of freshly-freed slot: assign
                    MUL2(a1p[s],  w, hx);
                    MUL2(a2p[s],  w, hy);
                    MUL2(assp[s], w, hss);
                    MUL2(axyp[s], w, hxy);
                } else {
                    FMA2(a1p[s],  w, hx,  a1p[s]);
                    FMA2(a2p[s],  w, hy,  a2p[s]);
                    FMA2(assp[s], w, hss, assp[s]);
                    FMA2(axyp[s], w, hxy, axyp[s]);
                }
            }

            // Output row oy = ir-10 completed this iteration (slot (j+1)%11).
            if (ir >= 10 && ir < TILE_H + 10) {
                const int s = (j + 1) % 11;
                u64 m11, m22, m12, msum, s12, svar, n1, n2, d1, d2, num, den;
                MUL2(m11, a1p[s], a1p[s]);
                MUL2(m22, a2p[s], a2p[s]);
                MUL2(m12, a1p[s], a2p[s]);
                ADD2(msum, m11, m22);                    // mu1^2 + mu2^2
                FMA2(s12,  m12,  NEG1p, axyp[s]);        // E[xy] - mu1mu2
                FMA2(svar, msum, NEG1p, assp[s]);        // s1 + s2
                FMA2(n1, m12, TWOp, C1p);                // 2*mu1mu2 + C1
                FMA2(n2, s12, TWOp, C2p);                // 2*s12 + C2
                ADD2(d1, msum, C1p);
                ADD2(d2, svar, C2p);
                MUL2(num, n1, n2);
                MUL2(den, d1, d2);
                float na, nb, da, db;
                UNPACK2(na, nb, num);
                UNPACK2(da, db, den);
                ssim_sum += __fdividef(na, da) + __fdividef(nb, db);
            }
        }
        __syncthreads();   // done reading buf before it is restaged at t+2
    }

    // Fold packed L1 lanes, then block reduction.
    float l1a, l1b;
    UNPACK2(l1a, l1b, l1p);
    float l1_sum = l1a + l1b;
#pragma unroll
    for (int off = 16; off; off >>= 1) {
        ssim_sum += __shfl_xor_sync(0xffffffffu, ssim_sum, off);
        l1_sum   += __shfl_xor_sync(0xffffffffu, l1_sum, off);
    }
    const int warp = tid >> 5;
    const int lane = tid & 31;
    if (lane == 0) {
        sred[warp] = ssim_sum;
        sred[warp + 4] = l1_sum;
    }
    __syncthreads();
    if (tid == 0) {
        const int bid = (blockIdx.z * GRID_Y + blockIdx.y) * GRID_X + blockIdx.x;
        g_partials[2 * bid]     = sred[0] + sred[1] + sred[2] + sred[3];
        g_partials[2 * bid + 1] = sred[4] + sred[5] + sred[6] + sred[7];
        __threadfence();
        const unsigned old = atomicInc(&g_count, NBLOCKS - 1);  // self-resetting
        s_last = (old == NBLOCKS - 1);
    }
    __syncthreads();

    // Last block folds the deterministic final reduction.
    if (s_last) {
        __shared__ double sd[8];
        double s = 0.0, l = 0.0;
        for (int i = tid; i < NBLOCKS; i += THREADS) {
            s += (double)g_partials[2 * i];
            l += (double)g_partials[2 * i + 1];
        }
#pragma unroll
        for (int off = 16; off; off >>= 1) {
            s += __shfl_xor_sync(0xffffffffu, s, off);
            l += __shfl_xor_sync(0xffffffffu, l, off);
        }
        if (lane == 0) { sd[warp] = s; sd[warp + 4] = l; }
        __syncthreads();
        if (tid == 0) {
            double ss = 0.0, ll = 0.0;
#pragma unroll
            for (int w = 0; w < 4; ++w) { ss += sd[w]; ll += sd[w + 4]; }
            out[0] = (float)(ll / NPIX + 1.0 - ss / NPIX);
        }
    }
}

extern "C" void kernel_launch(void* const* d_in, const int* in_sizes, int n_in,
                              void* d_out, int out_size) {
    (void)in_sizes; (void)n_in; (void)out_size;
    const float* img1 = (const float*)d_in[0];
    const float* img2 = (const float*)d_in[1];
    dim3 grid(GRID_X, GRID_Y, NPLANE);
    ssim_main<<<grid, THREADS>>>(img1, img2, (float*)d_out);
}

// round 16
// speedup vs baseline: 1.5458x; 1.5458x over previous
#include <cuda_runtime.h>
#include <cstdint>

namespace {

constexpr int IMG_H  = 512;
constexpr int IMG_W  = 512;
constexpr int NPLANE = 48;            // 16 * 3
constexpr int TILE_W = 256;           // thread t owns cols t and t+128
constexpr int TILE_H = 32;
constexpr int THREADS = 128;
constexpr int HALO = 5;
constexpr int IN_ROWS = TILE_H + 2 * HALO;          // 42 input rows needed
constexpr int NGROUPS = (IN_ROWS + 10) / 11;        // 4 groups of <=11 staged rows
constexpr int NPAIR = TILE_W / 2 + 2 * HALO;        // 138 interleaved pairs per row
constexpr int GRID_X = IMG_W / TILE_W;              // 2
constexpr int GRID_Y = IMG_H / TILE_H;              // 16
constexpr int NBLOCKS = GRID_X * GRID_Y * NPLANE;   // 1536
constexpr float C1v = 0.01f * 0.01f;
constexpr float C2v = 0.03f * 0.03f;
constexpr double NPIX = 12582912.0;                 // 16*3*512*512

__device__ constexpr float GW[11] = {
    0.0010283784f, 0.0075987582f, 0.0360008038f, 0.1093606949f, 0.2130055428f,
    0.2660117149f, 0.2130055428f, 0.1093606949f, 0.0360008038f, 0.0075987582f,
    0.0010283784f};

} // namespace

// ---- packed f32x2 helpers (SASS FFMA2 / FMUL2 / FADD2 — PTX-only forms) ----
typedef unsigned long long u64;
#define FMA2(d, a, b, c) \
    asm("fma.rn.f32x2 %0, %1, %2, %3;" : "=l"(d) : "l"(a), "l"(b), "l"(c))
#define MUL2(d, a, b) \
    asm("mul.rn.f32x2 %0, %1, %2;" : "=l"(d) : "l"(a), "l"(b))
#define ADD2(d, a, b) \
    asm("add.rn.f32x2 %0, %1, %2;" : "=l"(d) : "l"(a), "l"(b))
#define PACK2(d, lo, hi) \
    asm("mov.b64 %0, {%1, %2};" : "=l"(d) : "r"(__float_as_uint(lo)), "r"(__float_as_uint(hi)))
#define UNPACK2(lo, hi, d) \
    do { unsigned _ulo, _uhi; \
         asm("mov.b64 {%0, %1}, %2;" : "=r"(_ulo), "=r"(_uhi) : "l"(d)); \
         lo = __uint_as_float(_ulo); hi = __uint_as_float(_uhi); } while (0)

// ---- cp.async (LDGSTS) helpers: 4B copy with zero-fill when src_size==0 ----
#define CP4(dst_u32, src_ptr, sz) \
    asm volatile("cp.async.ca.shared.global [%0], [%1], 4, %2;" \
                 :: "r"(dst_u32), "l"(src_ptr), "r"(sz))
#define CP_COMMIT() asm volatile("cp.async.commit_group;")
#define CP_WAIT1()  asm volatile("cp.async.wait_group 1;")
#define CP_WAIT0()  asm volatile("cp.async.wait_group 0;")

__device__ float g_partials[NBLOCKS * 2];
__device__ unsigned int g_count = 0;

__global__ __launch_bounds__(THREADS, 4)
void ssim_main(const float* __restrict__ img1, const float* __restrict__ img2,
               float* __restrict__ out) {
    // Double-buffered interleaved pair layout (R10-proven):
    // sbuf[buf][arr][j][i] = pack(v[row, c0+i-5], v[row, c0+i+123]).
    __shared__ u64 sbuf[2][2][11][NPAIR];     // 48,576 B
    __shared__ float sred[8];
    __shared__ bool s_last;

    const int tid = threadIdx.x;
    const int c0 = blockIdx.x * TILE_W;
    const int r0 = blockIdx.y * TILE_H;
    const float* p1 = img1 + (size_t)blockIdx.z * (IMG_H * IMG_W);
    const float* p2 = img2 + (size_t)blockIdx.z * (IMG_H * IMG_W);

    unsigned smem_base;
    asm("{ .reg .u64 t; cvta.to.shared.u64 t, %1; cvt.u32.u64 %0, t; }"
        : "=r"(smem_base) : "l"(&sbuf[0][0][0][0]));

    // Stage group g (rows rbase..rbase+rows_g-1) into buffer b via cp.async.
    auto stage = [&](int g, int b) {
        const int rows_g = (g == NGROUPS - 1) ? (IN_ROWS - g * 11) : 11;
        const int rbase = r0 - HALO + g * 11;
        const int total = rows_g * NPAIR;
        for (int idx = tid; idx < total; idx += THREADS) {
            const int j = idx / NPAIR;
            const int i = idx - j * NPAIR;
            const int gr = rbase + j;
            const bool rin = (unsigned)gr < (unsigned)IMG_H;
            const int cA = c0 + i - HALO;
            const int cB = cA + (TILE_W / 2);
            const bool inA = rin && (unsigned)cA < (unsigned)IMG_W;
            const bool inB = rin && (unsigned)cB < (unsigned)IMG_W;
            const int offA = inA ? gr * IMG_W + cA : 0;
            const int offB = inB ? gr * IMG_W + cB : 0;
            const unsigned szA = inA ? 4u : 0u;
            const unsigned szB = inB ? 4u : 0u;
            const unsigned dx = smem_base + (unsigned)((((b * 2 + 0) * 11 + j) * NPAIR + i) * 8);
            const unsigned dy = smem_base + (unsigned)((((b * 2 + 1) * 11 + j) * NPAIR + i) * 8);
            CP4(dx,     p1 + offA, szA);
            CP4(dx + 4, p1 + offB, szB);
            CP4(dy,     p2 + offA, szA);
            CP4(dy + 4, p2 + offB, szB);
        }
        CP_COMMIT();
    };

    // 6 unique packed Gaussian weights (symmetric window).
    u64 wp[6];
#pragma unroll
    for (int k = 0; k < 6; ++k) PACK2(wp[k], GW[k], GW[k]);
    u64 NEG1p, C1p, C2p, TWOp;
    PACK2(NEG1p, -1.f, -1.f);
    PACK2(C1p, C1v, C1v);
    PACK2(C2p, C2v, C2v);
    PACK2(TWOp, 2.f, 2.f);

    // Vertical ring accumulators (packed), slot = output_row % 11.
    u64 a1p[11], a2p[11], assp[11], axyp[11];
#pragma unroll
    for (int i = 0; i < 11; ++i) {
        a1p[i] = 0ull; a2p[i] = 0ull; assp[i] = 0ull; axyp[i] = 0ull;
    }

    float ssim_sum = 0.f;
    u64 l1p = 0ull;   // packed |x-y| accumulator

    stage(0, 0);

    for (int t = 0; t < NGROUPS; ++t) {
        const int buf = t & 1;
        if (t + 1 < NGROUPS) {
            stage(t + 1, buf ^ 1);   // overlap next group's loads with compute
            CP_WAIT1();              // group t's data landed
        } else {
            CP_WAIT0();
        }
        __syncthreads();             // all threads' group-t cp.asyncs complete

#pragma unroll
        for (int j = 0; j < 11; ++j) {
            const int ir = t * 11 + j;   // staged input row index
            if (ir >= IN_ROWS) break;

            // Horizontal 11-tap conv of x, y, x^2+y^2, x*y — every tap is one
            // aligned LDS.64 that IS the packed operand.
            u64 hx, hy, hss, hxy;
            u64 l1x, l1y;
#pragma unroll
            for (int k = 0; k < 11; ++k) {
                const u64 xp = sbuf[buf][0][j][tid + k];
                const u64 yp = sbuf[buf][1][j][tid + k];
                if (k == HALO) { l1x = xp; l1y = yp; }
                u64 ssq, pxy, txx;
                MUL2(txx, xp, xp);
                FMA2(ssq, yp, yp, txx);      // x^2 + y^2
                MUL2(pxy, xp, yp);
                const u64 w = wp[k < 6 ? k : 10 - k];
                if (k == 0) {
                    MUL2(hx, w, xp);  MUL2(hy, w, yp);
                    MUL2(hss, w, ssq); MUL2(hxy, w, pxy);
                } else {
                    FMA2(hx,  w, xp,  hx);
                    FMA2(hy,  w, yp,  hy);
                    FMA2(hss, w, ssq, hss);
                    FMA2(hxy, w, pxy, hxy);
                }
            }

            // L1 term: once per pixel (both lanes at once).
            if (ir >= HALO && ir < TILE_H + HALO) {
                u64 d;
                FMA2(d, l1y, NEG1p, l1x);                  // x - y
                d &= 0x7FFFFFFF7FFFFFFFull;                // |.| per lane
                ADD2(l1p, l1p, d);
            }

            // Vertical ring accumulation (packed). slot = (ir - dy) % 11, static.
#pragma unroll
            for (int dy = 0; dy < 11; ++dy) {
                const int s = (j - dy + 11) % 11;
                const u64 w = wp[dy < 6 ? dy : 10 - dy];
                if (dy == 0) {   // first touch of freshly-freed slot: assign
                    MUL2(a1p[s],  w, hx);
                    MUL2(a2p[s],  w, hy);
                    MUL2(assp[s], w, hss);
                    MUL2(axyp[s], w, hxy);
                } else {
                    FMA2(a1p[s],  w, hx,  a1p[s]);
                    FMA2(a2p[s],  w, hy,  a2p[s]);
                    FMA2(assp[s], w, hss, assp[s]);
                    FMA2(axyp[s], w, hxy, axyp[s]);
                }
            }

            // Output row oy = ir-10 completed this iteration (slot (j+1)%11).
            if (ir >= 10 && ir < TILE_H + 10) {
                const int s = (j + 1) % 11;
                u64 m11, m22, m12, msum, s12, svar, n1, n2, d1, d2, num, den;
                MUL2(m11, a1p[s], a1p[s]);
                MUL2(m22, a2p[s], a2p[s]);
                MUL2(m12, a1p[s], a2p[s]);
                ADD2(msum, m11, m22);                    // mu1^2 + mu2^2
                FMA2(s12,  m12,  NEG1p, axyp[s]);        // E[xy] - mu1mu2
                FMA2(svar, msum, NEG1p, assp[s]);        // s1 + s2
                FMA2(n1, m12, TWOp, C1p);                // 2*mu1mu2 + C1
                FMA2(n2, s12, TWOp, C2p);                // 2*s12 + C2
                ADD2(d1, msum, C1p);
                ADD2(d2, svar, C2p);
                MUL2(num, n1, n2);
                MUL2(den, d1, d2);
                float na, nb, da, db;
                UNPACK2(na, nb, num);
                UNPACK2(da, db, den);
                ssim_sum += __fdividef(na, da) + __fdividef(nb, db);
            }
        }
        __syncthreads();   // done reading buf before it is restaged at t+2
    }

    // Fold packed L1 lanes, then block reduction.
    float l1a, l1b;
    UNPACK2(l1a, l1b, l1p);
    float l1_sum = l1a + l1b;
#pragma unroll
    for (int off = 16; off; off >>= 1) {
        ssim_sum += __shfl_xor_sync(0xffffffffu, ssim_sum, off);
        l1_sum   += __shfl_xor_sync(0xffffffffu, l1_sum, off);
    }
    const int warp = tid >> 5;
    const int lane = tid & 31;
    if (lane == 0) {
        sred[warp] = ssim_sum;
        sred[warp + 4] = l1_sum;
    }
    __syncthreads();
    if (tid == 0) {
        const int bid = (blockIdx.z * GRID_Y + blockIdx.y) * GRID_X + blockIdx.x;
        g_partials[2 * bid]     = sred[0] + sred[1] + sred[2] + sred[3];
        g_partials[2 * bid + 1] = sred[4] + sred[5] + sred[6] + sred[7];
        __threadfence();
        const unsigned old = atomicInc(&g_count, NBLOCKS - 1);  // self-resetting
        s_last = (old == NBLOCKS - 1);
    }
    __syncthreads();

    // Last block folds the deterministic final reduction.
    if (s_last) {
        __shared__ double sd[8];
        double s = 0.0, l = 0.0;
        for (int i = tid; i < NBLOCKS; i += THREADS) {
            s += (double)g_partials[2 * i];
            l += (double)g_partials[2 * i + 1];
        }
#pragma unroll
        for (int off = 16; off; off >>= 1) {
            s += __shfl_xor_sync(0xffffffffu, s, off);
            l += __shfl_xor_sync(0xffffffffu, l, off);
        }
        if (lane == 0) { sd[warp] = s; sd[warp + 4] = l; }
        __syncthreads();
        if (tid == 0) {
            double ss = 0.0, ll = 0.0;
#pragma unroll
            for (int w = 0; w < 4; ++w) { ss += sd[w]; ll += sd[w + 4]; }
            out[0] = (float)(ll / NPIX + 1.0 - ss / NPIX);
        }
    }
}

extern "C" void kernel_launch(void* const* d_in, const int* in_sizes, int n_in,
                              void* d_out, int out_size) {
    (void)in_sizes; (void)n_in; (void)out_size;
    const float* img1 = (const float*)d_in[0];
    const float* img2 = (const float*)d_in[1];
    dim3 grid(GRID_X, GRID_Y, NPLANE);
    ssim_main<<<grid, THREADS>>>(img1, img2, (float*)d_out);
}

// round 17
// speedup vs baseline: 1.6182x; 1.0468x over previous
#include <cuda_runtime.h>
#include <cstdint>

namespace {

constexpr int IMG_H  = 512;
constexpr int IMG_W  = 512;
constexpr int NPLANE = 48;            // 16 * 3
constexpr int TILE_W = 256;           // thread t owns cols t and t+128
constexpr int TILE_H = 128;
constexpr int THREADS = 128;
constexpr int HALO = 5;
constexpr int IN_ROWS = TILE_H + 2 * HALO;          // 138 input rows needed
constexpr int NGROUPS = (IN_ROWS + 10) / 11;        // 13 groups of <=11 staged rows
constexpr int NPAIR = TILE_W / 2 + 2 * HALO;        // 138 interleaved pairs per row
constexpr int GRID_X = IMG_W / TILE_W;              // 2
constexpr int GRID_Y = IMG_H / TILE_H;              // 4
constexpr int NBLOCKS = GRID_X * GRID_Y * NPLANE;   // 384 — single wave (cap 592)
constexpr float C1v = 0.01f * 0.01f;
constexpr float C2v = 0.03f * 0.03f;
constexpr double NPIX = 12582912.0;                 // 16*3*512*512

__device__ constexpr float GW[11] = {
    0.0010283784f, 0.0075987582f, 0.0360008038f, 0.1093606949f, 0.2130055428f,
    0.2660117149f, 0.2130055428f, 0.1093606949f, 0.0360008038f, 0.0075987582f,
    0.0010283784f};

} // namespace

// ---- packed f32x2 helpers (SASS FFMA2 / FMUL2 / FADD2 — PTX-only forms) ----
typedef unsigned long long u64;
#define FMA2(d, a, b, c) \
    asm("fma.rn.f32x2 %0, %1, %2, %3;" : "=l"(d) : "l"(a), "l"(b), "l"(c))
#define MUL2(d, a, b) \
    asm("mul.rn.f32x2 %0, %1, %2;" : "=l"(d) : "l"(a), "l"(b))
#define ADD2(d, a, b) \
    asm("add.rn.f32x2 %0, %1, %2;" : "=l"(d) : "l"(a), "l"(b))
#define PACK2(d, lo, hi) \
    asm("mov.b64 %0, {%1, %2};" : "=l"(d) : "r"(__float_as_uint(lo)), "r"(__float_as_uint(hi)))
#define UNPACK2(lo, hi, d) \
    do { unsigned _ulo, _uhi; \
         asm("mov.b64 {%0, %1}, %2;" : "=r"(_ulo), "=r"(_uhi) : "l"(d)); \
         lo = __uint_as_float(_ulo); hi = __uint_as_float(_uhi); } while (0)

// ---- cp.async (LDGSTS) helpers: 4B copy with zero-fill when src_size==0 ----
#define CP4(dst_u32, src_ptr, sz) \
    asm volatile("cp.async.ca.shared.global [%0], [%1], 4, %2;" \
                 :: "r"(dst_u32), "l"(src_ptr), "r"(sz))
#define CP_COMMIT() asm volatile("cp.async.commit_group;")
#define CP_WAIT1()  asm volatile("cp.async.wait_group 1;")
#define CP_WAIT0()  asm volatile("cp.async.wait_group 0;")

__device__ float g_partials[NBLOCKS * 2];
__device__ unsigned int g_count = 0;

__global__ __launch_bounds__(THREADS, 4)
void ssim_main(const float* __restrict__ img1, const float* __restrict__ img2,
               float* __restrict__ out) {
    // Double-buffered interleaved pair layout (R10-proven):
    // sbuf[buf][arr][j][i] = pack(v[row, c0+i-5], v[row, c0+i+123]).
    __shared__ u64 sbuf[2][2][11][NPAIR];     // 48,576 B
    __shared__ float sred[8];
    __shared__ bool s_last;

    const int tid = threadIdx.x;
    const int c0 = blockIdx.x * TILE_W;
    const int r0 = blockIdx.y * TILE_H;
    const float* p1 = img1 + (size_t)blockIdx.z * (IMG_H * IMG_W);
    const float* p2 = img2 + (size_t)blockIdx.z * (IMG_H * IMG_W);

    unsigned smem_base;
    asm("{ .reg .u64 t; cvta.to.shared.u64 t, %1; cvt.u32.u64 %0, t; }"
        : "=r"(smem_base) : "l"(&sbuf[0][0][0][0]));

    // Stage group g (rows rbase..rbase+rows_g-1) into buffer b via cp.async.
    auto stage = [&](int g, int b) {
        const int rows_g = (g == NGROUPS - 1) ? (IN_ROWS - g * 11) : 11;
        const int rbase = r0 - HALO + g * 11;
        const int total = rows_g * NPAIR;
        for (int idx = tid; idx < total; idx += THREADS) {
            const int j = idx / NPAIR;
            const int i = idx - j * NPAIR;
            const int gr = rbase + j;
            const bool rin = (unsigned)gr < (unsigned)IMG_H;
            const int cA = c0 + i - HALO;
            const int cB = cA + (TILE_W / 2);
            const bool inA = rin && (unsigned)cA < (unsigned)IMG_W;
            const bool inB = rin && (unsigned)cB < (unsigned)IMG_W;
            const int offA = inA ? gr * IMG_W + cA : 0;
            const int offB = inB ? gr * IMG_W + cB : 0;
            const unsigned szA = inA ? 4u : 0u;
            const unsigned szB = inB ? 4u : 0u;
            const unsigned dx = smem_base + (unsigned)((((b * 2 + 0) * 11 + j) * NPAIR + i) * 8);
            const unsigned dy = smem_base + (unsigned)((((b * 2 + 1) * 11 + j) * NPAIR + i) * 8);
            CP4(dx,     p1 + offA, szA);
            CP4(dx + 4, p1 + offB, szB);
            CP4(dy,     p2 + offA, szA);
            CP4(dy + 4, p2 + offB, szB);
        }
        CP_COMMIT();
    };

    // 6 unique packed Gaussian weights (symmetric window).
    u64 wp[6];
#pragma unroll
    for (int k = 0; k < 6; ++k) PACK2(wp[k], GW[k], GW[k]);
    u64 NEG1p, C1p, C2p, TWOp;
    PACK2(NEG1p, -1.f, -1.f);
    PACK2(C1p, C1v, C1v);
    PACK2(C2p, C2v, C2v);
    PACK2(TWOp, 2.f, 2.f);

    // Vertical ring accumulators (packed), slot = output_row % 11.
    u64 a1p[11], a2p[11], assp[11], axyp[11];
#pragma unroll
    for (int i = 0; i < 11; ++i) {
        a1p[i] = 0ull; a2p[i] = 0ull; assp[i] = 0ull; axyp[i] = 0ull;
    }

    float ssim_sum = 0.f;
    u64 l1p = 0ull;   // packed |x-y| accumulator

    stage(0, 0);

    for (int t = 0; t < NGROUPS; ++t) {
        const int buf = t & 1;
        if (t + 1 < NGROUPS) {
            stage(t + 1, buf ^ 1);   // overlap next group's loads with compute
            CP_WAIT1();              // group t's data landed
        } else {
            CP_WAIT0();
        }
        __syncthreads();             // all threads' group-t cp.asyncs complete

#pragma unroll
        for (int j = 0; j < 11; ++j) {
            const int ir = t * 11 + j;   // staged input row index
            if (ir >= IN_ROWS) break;

            // Horizontal 11-tap conv of x, y, x^2+y^2, x*y — every tap is one
            // aligned LDS.64 that IS the packed operand.
            u64 hx, hy, hss, hxy;
            u64 l1x, l1y;
#pragma unroll
            for (int k = 0; k < 11; ++k) {
                const u64 xp = sbuf[buf][0][j][tid + k];
                const u64 yp = sbuf[buf][1][j][tid + k];
                if (k == HALO) { l1x = xp; l1y = yp; }
                u64 ssq, pxy, txx;
                MUL2(txx, xp, xp);
                FMA2(ssq, yp, yp, txx);      // x^2 + y^2
                MUL2(pxy, xp, yp);
                const u64 w = wp[k < 6 ? k : 10 - k];
                if (k == 0) {
                    MUL2(hx, w, xp);  MUL2(hy, w, yp);
                    MUL2(hss, w, ssq); MUL2(hxy, w, pxy);
                } else {
                    FMA2(hx,  w, xp,  hx);
                    FMA2(hy,  w, yp,  hy);
                    FMA2(hss, w, ssq, hss);
                    FMA2(hxy, w, pxy, hxy);
                }
            }

            // L1 term: once per pixel (both lanes at once).
            if (ir >= HALO && ir < TILE_H + HALO) {
                u64 d;
                FMA2(d, l1y, NEG1p, l1x);                  // x - y
                d &= 0x7FFFFFFF7FFFFFFFull;                // |.| per lane
                ADD2(l1p, l1p, d);
            }

            // Vertical ring accumulation (packed). slot = (ir - dy) % 11, static.
#pragma unroll
            for (int dy = 0; dy < 11; ++dy) {
                const int s = (j - dy + 11) % 11;
                const u64 w = wp[dy < 6 ? dy : 10 - dy];
                if (dy == 0) {   // first touch of freshly-freed slot: assign
                    MUL2(a1p[s],  w, hx);
                    MUL2(a2p[s],  w, hy);
                    MUL2(assp[s], w, hss);
                    MUL2(axyp[s], w, hxy);
                } else {
                    FMA2(a1p[s],  w, hx,  a1p[s]);
                    FMA2(a2p[s],  w, hy,  a2p[s]);
                    FMA2(assp[s], w, hss, assp[s]);
                    FMA2(axyp[s], w, hxy, axyp[s]);
                }
            }

            // Output row oy = ir-10 completed this iteration (slot (j+1)%11).
            if (ir >= 10 && ir < TILE_H + 10) {
                const int s = (j + 1) % 11;
                u64 m11, m22, m12, msum, s12, svar, n1, n2, d1, d2, num, den;
                MUL2(m11, a1p[s], a1p[s]);
                MUL2(m22, a2p[s], a2p[s]);
                MUL2(m12, a1p[s], a2p[s]);
                ADD2(msum, m11, m22);                    // mu1^2 + mu2^2
                FMA2(s12,  m12,  NEG1p, axyp[s]);        // E[xy] - mu1mu2
                FMA2(svar, msum, NEG1p, assp[s]);        // s1 + s2
                FMA2(n1, m12, TWOp, C1p);                // 2*mu1mu2 + C1
                FMA2(n2, s12, TWOp, C2p);                // 2*s12 + C2
                ADD2(d1, msum, C1p);
                ADD2(d2, svar, C2p);
                MUL2(num, n1, n2);
                MUL2(den, d1, d2);
                float na, nb, da, db;
                UNPACK2(na, nb, num);
                UNPACK2(da, db, den);
                ssim_sum += __fdividef(na, da) + __fdividef(nb, db);
            }
        }
        __syncthreads();   // done reading buf before it is restaged at t+2
    }

    // Fold packed L1 lanes, then block reduction.
    float l1a, l1b;
    UNPACK2(l1a, l1b, l1p);
    float l1_sum = l1a + l1b;
#pragma unroll
    for (int off = 16; off; off >>= 1) {
        ssim_sum += __shfl_xor_sync(0xffffffffu, ssim_sum, off);
        l1_sum   += __shfl_xor_sync(0xffffffffu, l1_sum, off);
    }
    const int warp = tid >> 5;
    const int lane = tid & 31;
    if (lane == 0) {
        sred[warp] = ssim_sum;
        sred[warp + 4] = l1_sum;
    }
    __syncthreads();
    if (tid == 0) {
        const int bid = (blockIdx.z * GRID_Y + blockIdx.y) * GRID_X + blockIdx.x;
        g_partials[2 * bid]     = sred[0] + sred[1] + sred[2] + sred[3];
        g_partials[2 * bid + 1] = sred[4] + sred[5] + sred[6] + sred[7];
        __threadfence();
        const unsigned old = atomicInc(&g_count, NBLOCKS - 1);  // self-resetting
        s_last = (old == NBLOCKS - 1);
    }
    __syncthreads();

    // Last block folds the deterministic final reduction.
    if (s_last) {
        __shared__ double sd[8];
        double s = 0.0, l = 0.0;
        for (int i = tid; i < NBLOCKS; i += THREADS) {
            s += (double)g_partials[2 * i];
            l += (double)g_partials[2 * i + 1];
        }
#pragma unroll
        for (int off = 16; off; off >>= 1) {
            s += __shfl_xor_sync(0xffffffffu, s, off);
            l += __shfl_xor_sync(0xffffffffu, l, off);
        }
        if (lane == 0) { sd[warp] = s; sd[warp + 4] = l; }
        __syncthreads();
        if (tid == 0) {
            double ss = 0.0, ll = 0.0;
#pragma unroll
            for (int w = 0; w < 4; ++w) { ss += sd[w]; ll += sd[w + 4]; }
            out[0] = (float)(ll / NPIX + 1.0 - ss / NPIX);
        }
    }
}

extern "C" void kernel_launch(void* const* d_in, const int* in_sizes, int n_in,
                              void* d_out, int out_size) {
    (void)in_sizes; (void)n_in; (void)out_size;
    const float* img1 = (const float*)d_in[0];
    const float* img2 = (const float*)d_in[1];
    dim3 grid(GRID_X, GRID_Y, NPLANE);
    ssim_main<<<grid, THREADS>>>(img1, img2, (float*)d_out);
}